// round 7
// baseline (speedup 1.0000x reference)
#include <cuda_runtime.h>

// LSTM seq2seq: encoder (1->64) over T=1000, decoder (1->65) with teacher
// forcing over T=1000, output Linear(65->1). B=2048.
//
// Round 7: round-4 structure (256 thr, 2 CTA/SM, thread=(pair,half) owns
// 2 gate rows x 32-col k-half, 1-shfl combine), plus:
//  - gate phase processes ALL bt batch rows in one block (NB=7/6): 14
//    independent FFMA2 chains + 7 parallel LDS streams, single tail
//  - cell state c lives in registers across the scan (smem only at the
//    enc->dec transition)
//  - loop-invariant LDS/address math hoisted out of the 1000-step loop

#define T_STEPS   1000
#define BATCH     2048
#define NCTA      296
#define NTHREADS  256
#define NWARPS    (NTHREADS / 32)
#define BT_MAX    7
#define HP        72     // h row pitch; cols0-31 at +0, cols32-63 at +36, col64 at +68
#define GP        264    // gates row pitch

typedef unsigned long long u64;

struct Smem {
    float h[BT_MAX * HP];   // split layout
    float c[BT_MAX * HP];   // linear; used only for init + enc->dec transition
    float gates[BT_MAX * GP];
    float xbuf[2][BT_MAX];
    float xw[4 * 68];       // decoder gate rows 256..259 (65 weights, linear)
    float xwih[4];
    float xbias[4];
    float linW[68];
};

__device__ __forceinline__ u64 pack2(float lo, float hi) {
    u64 r;
    asm("mov.b64 %0, {%1, %2};" : "=l"(r) : "f"(lo), "f"(hi));
    return r;
}
__device__ __forceinline__ float2 unpack2(u64 v) {
    float lo, hi;
    asm("mov.b64 {%0, %1}, %2;" : "=f"(lo), "=f"(hi) : "l"(v));
    return make_float2(lo, hi);
}
__device__ __forceinline__ void ffma2(u64& d, u64 a, u64 b, u64 c) {
    asm("fma.rn.f32x2 %0, %1, %2, %3;" : "=l"(d) : "l"(a), "l"(b), "l"(c));
}

__device__ __forceinline__ float sigf(float x) {
    return __fdividef(1.0f, 1.0f + __expf(-x));
}
__device__ __forceinline__ float tanh_fast(float x) {
    float ax = fminf(fabsf(x), 15.0f);
    float e  = __expf(2.0f * ax);
    float t  = 1.0f - __fdividef(2.0f, e + 1.0f);
    return copysignf(t, x);
}

// All-batch gate phase: NB rows at once. w2[0..15]=row r0 pairs,
// w2[16..31]=row r1 pairs (this thread's 32-col k-half).
template <int H, int NB>
__device__ __forceinline__ void gate_all(
    Smem& sm, const float* xs,
    const u64* w2, float wrem0, float wrem1,
    float wih_g, float bias_g, int tid, int half)
{
    // hoist x and (dec) h64 values; broadcast LDS issued up front
    float xv[NB];
#pragma unroll
    for (int u = 0; u < NB; u++) xv[u] = xs[u];
    float h64[NB];
    if constexpr (H == 65) {
#pragma unroll
        for (int u = 0; u < NB; u++) h64[u] = sm.h[u * HP + 68];
    }

    u64 a0[NB], a1[NB];
#pragma unroll
    for (int u = 0; u < NB; u++) { a0[u] = 0ull; a1[u] = 0ull; }

    // row stride 72 floats = 288 B = 18 ulonglong2; half offset 144 B
    const ulonglong2* hp = (const ulonglong2*)((const char*)sm.h + half * 144);
#pragma unroll
    for (int q = 0; q < 8; q++) {
#pragma unroll
        for (int u = 0; u < NB; u++) {
            ulonglong2 h2 = hp[u * 18 + q];   // 2 disjoint-bank broadcast groups
            ffma2(a0[u], w2[2 * q],      h2.x, a0[u]);
            ffma2(a0[u], w2[2 * q + 1],  h2.y, a0[u]);
            ffma2(a1[u], w2[16 + 2 * q], h2.x, a1[u]);
            ffma2(a1[u], w2[17 + 2 * q], h2.y, a1[u]);
        }
    }
#pragma unroll
    for (int u = 0; u < NB; u++) {
        float2 s0 = unpack2(a0[u]);
        float2 s1 = unpack2(a1[u]);
        float p0 = s0.x + s0.y;
        float p1 = s1.x + s1.y;
        if constexpr (H == 65) {
            p0 = fmaf(wrem0, h64[u], p0);
            p1 = fmaf(wrem1, h64[u], p1);
        }
        const float send = half ? p0 : p1;
        const float recv = __shfl_xor_sync(0xffffffffu, send, 1);
        const float own  = half ? p1 : p0;
        sm.gates[u * GP + tid] = fmaf(wih_g, xv[u], bias_g + own + recv);
    }
}

template <int H, bool IS_DEC>
__device__ __forceinline__ void lstm_scan(
    Smem& sm, int bt, int b0,
    const float* __restrict__ xglob,
    const float* __restrict__ Wih,
    const float* __restrict__ Whh,
    const float* __restrict__ bih,
    const float* __restrict__ bhh,
    float* __restrict__ out,
    float linb)
{
    const int tid  = threadIdx.x;
    const int wid  = tid >> 5;
    const int lane = tid & 31;
    const int pair = tid >> 1;
    const int half = tid & 1;

    // ---- weight tile: rows {2p, 2p+1}, cols [32*half, 32*half+32) ----
    u64   w2[32];
    float wrem0 = 0.0f, wrem1 = 0.0f;
    float wih_g, bias_g;
    {
        const int r0 = 2 * pair, r1 = r0 + 1;
        const float* wr0 = Whh + r0 * H + half * 32;
        const float* wr1 = Whh + r1 * H + half * 32;
#pragma unroll
        for (int p = 0; p < 16; p++) {
            w2[p]      = pack2(wr0[2 * p], wr0[2 * p + 1]);
            w2[16 + p] = pack2(wr1[2 * p], wr1[2 * p + 1]);
        }
        if constexpr (H == 65) {
            if (half) {
                wrem0 = Whh[r0 * H + 64];
                wrem1 = Whh[r1 * H + 64];
            }
        }
        wih_g  = Wih[tid];
        bias_g = bih[tid] + bhh[tid];
    }

    // ---- precompute update mapping + addresses (loop-invariant) ----
    int ucnt = 0;
    int ga[2], ha[2], ca[2];
    {
        const int npairs = H * bt;
        for (int p = tid; p < npairs; p += NTHREADS) {
            const int b = p / H;
            const int j = p - b * H;
            ga[ucnt] = b * GP + j;
            ca[ucnt] = b * HP + j;
            ha[ucnt] = b * HP + ((j < 32) ? j : (j + 4));
            ucnt++;
        }
    }
    // c lives in registers across the scan; initial value from smem
    float cr[2];
#pragma unroll
    for (int k = 0; k < 2; k++)
        cr[k] = (k < ucnt) ? sm.c[ca[k]] : 0.0f;

    // ---- decoder loop-invariant hoists ----
    float lw0 = 0.0f, lw1 = 0.0f, lw64 = 0.0f;
    int   tcnt = 0;
    int   te[4], tb[4];
    float twe0[4], twe1[4];
    if constexpr (IS_DEC) {
        lw0  = sm.linW[lane];
        lw1  = sm.linW[lane + 32];
        lw64 = sm.linW[64];
        const int ntask = 4 * bt;
        for (int task = wid; task < ntask && tcnt < 4; task += NWARPS) {
            const int e = task & 3;
            te[tcnt]   = e;
            tb[tcnt]   = task >> 2;
            twe0[tcnt] = sm.xw[e * 68 + lane];
            twe1[tcnt] = sm.xw[e * 68 + lane + 32];
            tcnt++;
        }
    }

    for (int t = 0; t < T_STEPS; t++) {
        float xnext = 0.0f;
        const bool do_pref = (tid < bt) && (t + 1 < T_STEPS);
        if (do_pref) {
            const int row = IS_DEC ? t : (t + 1);
            xnext = xglob[row * BATCH + b0 + tid];
        }
        const float* xs = sm.xbuf[t & 1];

        // ---- gate phase (all batch rows in one block) ----
        if (bt == 7) gate_all<H, 7>(sm, xs, w2, wrem0, wrem1, wih_g, bias_g, tid, half);
        else         gate_all<H, 6>(sm, xs, w2, wrem0, wrem1, wih_g, bias_g, tid, half);

        // ---- decoder: leftover gate rows 256..259, warp-cooperative ----
        if constexpr (IS_DEC) {
#pragma unroll
            for (int i = 0; i < 4; i++) {
                if (i < tcnt) {
                    const int e = te[i], b = tb[i];
                    const float* hrow = sm.h + b * HP;
                    float p = twe0[i] * hrow[lane] + twe1[i] * hrow[36 + lane];
                    if (lane == 0)
                        p += sm.xw[e * 68 + 64] * hrow[68];
#pragma unroll
                    for (int off = 16; off; off >>= 1)
                        p += __shfl_down_sync(0xffffffffu, p, off);
                    if (lane == 0)
                        sm.gates[b * GP + 256 + e] =
                            sm.xbias[e] + sm.xwih[e] * xs[b] + p;
                }
            }
        }

        if (do_pref) sm.xbuf[(t + 1) & 1][tid] = xnext;
        __syncthreads();

        // ---- pointwise LSTM update (c in registers) ----
#pragma unroll
        for (int k = 0; k < 2; k++) {
            if (k < ucnt) {
                const float gi = sm.gates[ga[k]];
                const float gf = sm.gates[ga[k] + H];
                const float gg = sm.gates[ga[k] + 2 * H];
                const float go = sm.gates[ga[k] + 3 * H];
                float cn = sigf(gf) * cr[k] + sigf(gi) * tanh_fast(gg);
                cr[k] = cn;
                sm.h[ha[k]] = sigf(go) * tanh_fast(cn);
            }
        }
        __syncthreads();

        // ---- decoder: output projection ----
        if constexpr (IS_DEC) {
            for (int b = wid; b < bt; b += NWARPS) {
                const float* hrow = sm.h + b * HP;
                float p = lw0 * hrow[lane] + lw1 * hrow[36 + lane];
                if (lane == 0) p += lw64 * hrow[68];
#pragma unroll
                for (int off = 16; off; off >>= 1)
                    p += __shfl_down_sync(0xffffffffu, p, off);
                if (lane == 0)
                    out[t * BATCH + b0 + b] = p + linb;
            }
        }
    }

    // ---- write final c back (needed for enc->dec transition) ----
#pragma unroll
    for (int k = 0; k < 2; k++)
        if (k < ucnt) sm.c[ca[k]] = cr[k];
}

__global__ void __launch_bounds__(NTHREADS, 2)
lstm_seq2seq_kernel(
    const float* __restrict__ input,  const float* __restrict__ speed,
    const float* __restrict__ target,
    const float* __restrict__ eWih,   const float* __restrict__ eWhh,
    const float* __restrict__ ebih,   const float* __restrict__ ebhh,
    const float* __restrict__ dWih,   const float* __restrict__ dWhh,
    const float* __restrict__ dbih,   const float* __restrict__ dbhh,
    const float* __restrict__ linW,   const float* __restrict__ linb,
    const float* __restrict__ denseW, const float* __restrict__ denseb,
    float* __restrict__ out)
{
    __shared__ Smem sm;
    const int tid  = threadIdx.x;
    const int cta  = blockIdx.x;
    const int base = BATCH / NCTA;     // 6
    const int rem  = BATCH % NCTA;     // 272
    const int bt   = base + (cta < rem ? 1 : 0);
    const int b0   = cta * base + min(cta, rem);

    for (int i = tid; i < BT_MAX * HP; i += NTHREADS) {
        sm.h[i] = 0.0f;
        sm.c[i] = 0.0f;
    }
    for (int i = tid; i < 4 * 65; i += NTHREADS) {
        const int e = i / 65, k = i - e * 65;
        sm.xw[e * 68 + k] = dWhh[(256 + e) * 65 + k];
    }
    if (tid < 4) {
        sm.xwih[tid]  = dWih[256 + tid];
        sm.xbias[tid] = dbih[256 + tid] + dbhh[256 + tid];
    }
    for (int i = tid; i < 65; i += NTHREADS) sm.linW[i] = linW[i];
    if (tid < bt) sm.xbuf[0][tid] = input[b0 + tid];
    const float lb = linb[0];
    __syncthreads();

    // ---- encoder scan (H=64) ----
    lstm_scan<64, false>(sm, bt, b0, input, eWih, eWhh, ebih, ebhh, nullptr, 0.0f);

    // ---- transition: append Dense(speed) to hidden & cell, zero dec x0 ----
    if (tid < bt) {
        const float sp = denseb[0] + denseW[0] * speed[b0 + tid];
        sm.h[tid * HP + 68] = sp;      // h split layout: col 64 at +68
        sm.c[tid * HP + 64] = sp;      // c linear
        sm.xbuf[0][tid] = 0.0f;
    }
    __syncthreads();

    // ---- decoder scan (H=65) + output projection ----
    lstm_scan<65, true>(sm, bt, b0, target, dWih, dWhh, dbih, dbhh, out, lb);
}

extern "C" void kernel_launch(void* const* d_in, const int* in_sizes, int n_in,
                              void* d_out, int out_size)
{
    const float* input  = (const float*)d_in[0];
    const float* speed  = (const float*)d_in[1];
    const float* target = (const float*)d_in[2];
    const float* eWih   = (const float*)d_in[3];
    const float* eWhh   = (const float*)d_in[4];
    const float* ebih   = (const float*)d_in[5];
    const float* ebhh   = (const float*)d_in[6];
    const float* dWih   = (const float*)d_in[7];
    const float* dWhh   = (const float*)d_in[8];
    const float* dbih   = (const float*)d_in[9];
    const float* dbhh   = (const float*)d_in[10];
    const float* linW   = (const float*)d_in[11];
    const float* linb   = (const float*)d_in[12];
    const float* denseW = (const float*)d_in[13];
    const float* denseb = (const float*)d_in[14];
    float* out = (float*)d_out;

    lstm_seq2seq_kernel<<<NCTA, NTHREADS>>>(
        input, speed, target,
        eWih, eWhh, ebih, ebhh,
        dWih, dWhh, dbih, dbhh,
        linW, linb, denseW, denseb, out);
}

// round 8
// speedup vs baseline: 1.0132x; 1.0132x over previous
#include <cuda_runtime.h>

// LSTM seq2seq: encoder (1->64) over T=1000, decoder (1->65) with teacher
// forcing over T=1000, output Linear(65->1). B=2048.
//
// Round 7: round-4 structure (256 thr, 2 CTA/SM, thread=(pair,half) owns
// 2 gate rows x 32-col k-half, 1-shfl combine), plus:
//  - gate phase processes ALL bt batch rows in one block (NB=7/6): 14
//    independent FFMA2 chains + 7 parallel LDS streams, single tail
//  - cell state c lives in registers across the scan (smem only at the
//    enc->dec transition)
//  - loop-invariant LDS/address math hoisted out of the 1000-step loop

#define T_STEPS   1000
#define BATCH     2048
#define NCTA      296
#define NTHREADS  256
#define NWARPS    (NTHREADS / 32)
#define BT_MAX    7
#define HP        72     // h row pitch; cols0-31 at +0, cols32-63 at +36, col64 at +68
#define GP        264    // gates row pitch

typedef unsigned long long u64;

struct Smem {
    float h[BT_MAX * HP];   // split layout
    float c[BT_MAX * HP];   // linear; used only for init + enc->dec transition
    float gates[BT_MAX * GP];
    float xbuf[2][BT_MAX];
    float xw[4 * 68];       // decoder gate rows 256..259 (65 weights, linear)
    float xwih[4];
    float xbias[4];
    float linW[68];
};

__device__ __forceinline__ u64 pack2(float lo, float hi) {
    u64 r;
    asm("mov.b64 %0, {%1, %2};" : "=l"(r) : "f"(lo), "f"(hi));
    return r;
}
__device__ __forceinline__ float2 unpack2(u64 v) {
    float lo, hi;
    asm("mov.b64 {%0, %1}, %2;" : "=f"(lo), "=f"(hi) : "l"(v));
    return make_float2(lo, hi);
}
__device__ __forceinline__ void ffma2(u64& d, u64 a, u64 b, u64 c) {
    asm("fma.rn.f32x2 %0, %1, %2, %3;" : "=l"(d) : "l"(a), "l"(b), "l"(c));
}

__device__ __forceinline__ float sigf(float x) {
    return __fdividef(1.0f, 1.0f + __expf(-x));
}
__device__ __forceinline__ float tanh_fast(float x) {
    float ax = fminf(fabsf(x), 15.0f);
    float e  = __expf(2.0f * ax);
    float t  = 1.0f - __fdividef(2.0f, e + 1.0f);
    return copysignf(t, x);
}

// All-batch gate phase: NB rows at once. w2[0..15]=row r0 pairs,
// w2[16..31]=row r1 pairs (this thread's 32-col k-half).
template <int H, int NB>
__device__ __forceinline__ void gate_all(
    Smem& sm, const float* xs,
    const u64* w2, float wrem0, float wrem1,
    float wih_g, float bias_g, int tid, int half)
{
    // hoist x and (dec) h64 values; broadcast LDS issued up front
    float xv[NB];
#pragma unroll
    for (int u = 0; u < NB; u++) xv[u] = xs[u];
    float h64[NB];
    if constexpr (H == 65) {
#pragma unroll
        for (int u = 0; u < NB; u++) h64[u] = sm.h[u * HP + 68];
    }

    u64 a0[NB], a1[NB];
#pragma unroll
    for (int u = 0; u < NB; u++) { a0[u] = 0ull; a1[u] = 0ull; }

    // row stride 72 floats = 288 B = 18 ulonglong2; half offset 144 B
    const ulonglong2* hp = (const ulonglong2*)((const char*)sm.h + half * 144);
#pragma unroll
    for (int q = 0; q < 8; q++) {
#pragma unroll
        for (int u = 0; u < NB; u++) {
            ulonglong2 h2 = hp[u * 18 + q];   // 2 disjoint-bank broadcast groups
            ffma2(a0[u], w2[2 * q],      h2.x, a0[u]);
            ffma2(a0[u], w2[2 * q + 1],  h2.y, a0[u]);
            ffma2(a1[u], w2[16 + 2 * q], h2.x, a1[u]);
            ffma2(a1[u], w2[17 + 2 * q], h2.y, a1[u]);
        }
    }
#pragma unroll
    for (int u = 0; u < NB; u++) {
        float2 s0 = unpack2(a0[u]);
        float2 s1 = unpack2(a1[u]);
        float p0 = s0.x + s0.y;
        float p1 = s1.x + s1.y;
        if constexpr (H == 65) {
            p0 = fmaf(wrem0, h64[u], p0);
            p1 = fmaf(wrem1, h64[u], p1);
        }
        const float send = half ? p0 : p1;
        const float recv = __shfl_xor_sync(0xffffffffu, send, 1);
        const float own  = half ? p1 : p0;
        sm.gates[u * GP + tid] = fmaf(wih_g, xv[u], bias_g + own + recv);
    }
}

template <int H, bool IS_DEC>
__device__ __forceinline__ void lstm_scan(
    Smem& sm, int bt, int b0,
    const float* __restrict__ xglob,
    const float* __restrict__ Wih,
    const float* __restrict__ Whh,
    const float* __restrict__ bih,
    const float* __restrict__ bhh,
    float* __restrict__ out,
    float linb)
{
    const int tid  = threadIdx.x;
    const int wid  = tid >> 5;
    const int lane = tid & 31;
    const int pair = tid >> 1;
    const int half = tid & 1;

    // ---- weight tile: rows {2p, 2p+1}, cols [32*half, 32*half+32) ----
    u64   w2[32];
    float wrem0 = 0.0f, wrem1 = 0.0f;
    float wih_g, bias_g;
    {
        const int r0 = 2 * pair, r1 = r0 + 1;
        const float* wr0 = Whh + r0 * H + half * 32;
        const float* wr1 = Whh + r1 * H + half * 32;
#pragma unroll
        for (int p = 0; p < 16; p++) {
            w2[p]      = pack2(wr0[2 * p], wr0[2 * p + 1]);
            w2[16 + p] = pack2(wr1[2 * p], wr1[2 * p + 1]);
        }
        if constexpr (H == 65) {
            if (half) {
                wrem0 = Whh[r0 * H + 64];
                wrem1 = Whh[r1 * H + 64];
            }
        }
        wih_g  = Wih[tid];
        bias_g = bih[tid] + bhh[tid];
    }

    // ---- precompute update mapping + addresses (loop-invariant) ----
    int ucnt = 0;
    int ga[2], ha[2], ca[2];
    {
        const int npairs = H * bt;
        for (int p = tid; p < npairs; p += NTHREADS) {
            const int b = p / H;
            const int j = p - b * H;
            ga[ucnt] = b * GP + j;
            ca[ucnt] = b * HP + j;
            ha[ucnt] = b * HP + ((j < 32) ? j : (j + 4));
            ucnt++;
        }
    }
    // c lives in registers across the scan; initial value from smem
    float cr[2];
#pragma unroll
    for (int k = 0; k < 2; k++)
        cr[k] = (k < ucnt) ? sm.c[ca[k]] : 0.0f;

    // ---- decoder loop-invariant hoists ----
    float lw0 = 0.0f, lw1 = 0.0f, lw64 = 0.0f;
    int   tcnt = 0;
    int   te[4], tb[4];
    float twe0[4], twe1[4];
    if constexpr (IS_DEC) {
        lw0  = sm.linW[lane];
        lw1  = sm.linW[lane + 32];
        lw64 = sm.linW[64];
        const int ntask = 4 * bt;
        for (int task = wid; task < ntask && tcnt < 4; task += NWARPS) {
            const int e = task & 3;
            te[tcnt]   = e;
            tb[tcnt]   = task >> 2;
            twe0[tcnt] = sm.xw[e * 68 + lane];
            twe1[tcnt] = sm.xw[e * 68 + lane + 32];
            tcnt++;
        }
    }

    for (int t = 0; t < T_STEPS; t++) {
        float xnext = 0.0f;
        const bool do_pref = (tid < bt) && (t + 1 < T_STEPS);
        if (do_pref) {
            const int row = IS_DEC ? t : (t + 1);
            xnext = xglob[row * BATCH + b0 + tid];
        }
        const float* xs = sm.xbuf[t & 1];

        // ---- gate phase (all batch rows in one block) ----
        if (bt == 7) gate_all<H, 7>(sm, xs, w2, wrem0, wrem1, wih_g, bias_g, tid, half);
        else         gate_all<H, 6>(sm, xs, w2, wrem0, wrem1, wih_g, bias_g, tid, half);

        // ---- decoder: leftover gate rows 256..259, warp-cooperative ----
        if constexpr (IS_DEC) {
#pragma unroll
            for (int i = 0; i < 4; i++) {
                if (i < tcnt) {
                    const int e = te[i], b = tb[i];
                    const float* hrow = sm.h + b * HP;
                    float p = twe0[i] * hrow[lane] + twe1[i] * hrow[36 + lane];
                    if (lane == 0)
                        p += sm.xw[e * 68 + 64] * hrow[68];
#pragma unroll
                    for (int off = 16; off; off >>= 1)
                        p += __shfl_down_sync(0xffffffffu, p, off);
                    if (lane == 0)
                        sm.gates[b * GP + 256 + e] =
                            sm.xbias[e] + sm.xwih[e] * xs[b] + p;
                }
            }
        }

        if (do_pref) sm.xbuf[(t + 1) & 1][tid] = xnext;
        __syncthreads();

        // ---- pointwise LSTM update (c in registers) ----
#pragma unroll
        for (int k = 0; k < 2; k++) {
            if (k < ucnt) {
                const float gi = sm.gates[ga[k]];
                const float gf = sm.gates[ga[k] + H];
                const float gg = sm.gates[ga[k] + 2 * H];
                const float go = sm.gates[ga[k] + 3 * H];
                float cn = sigf(gf) * cr[k] + sigf(gi) * tanh_fast(gg);
                cr[k] = cn;
                sm.h[ha[k]] = sigf(go) * tanh_fast(cn);
            }
        }
        __syncthreads();

        // ---- decoder: output projection ----
        if constexpr (IS_DEC) {
            for (int b = wid; b < bt; b += NWARPS) {
                const float* hrow = sm.h + b * HP;
                float p = lw0 * hrow[lane] + lw1 * hrow[36 + lane];
                if (lane == 0) p += lw64 * hrow[68];
#pragma unroll
                for (int off = 16; off; off >>= 1)
                    p += __shfl_down_sync(0xffffffffu, p, off);
                if (lane == 0)
                    out[t * BATCH + b0 + b] = p + linb;
            }
        }
    }

    // ---- write final c back (needed for enc->dec transition) ----
#pragma unroll
    for (int k = 0; k < 2; k++)
        if (k < ucnt) sm.c[ca[k]] = cr[k];
}

__global__ void __launch_bounds__(NTHREADS, 2)
lstm_seq2seq_kernel(
    const float* __restrict__ input,  const float* __restrict__ speed,
    const float* __restrict__ target,
    const float* __restrict__ eWih,   const float* __restrict__ eWhh,
    const float* __restrict__ ebih,   const float* __restrict__ ebhh,
    const float* __restrict__ dWih,   const float* __restrict__ dWhh,
    const float* __restrict__ dbih,   const float* __restrict__ dbhh,
    const float* __restrict__ linW,   const float* __restrict__ linb,
    const float* __restrict__ denseW, const float* __restrict__ denseb,
    float* __restrict__ out)
{
    __shared__ Smem sm;
    const int tid  = threadIdx.x;
    const int cta  = blockIdx.x;
    const int base = BATCH / NCTA;     // 6
    const int rem  = BATCH % NCTA;     // 272
    const int bt   = base + (cta < rem ? 1 : 0);
    const int b0   = cta * base + min(cta, rem);

    for (int i = tid; i < BT_MAX * HP; i += NTHREADS) {
        sm.h[i] = 0.0f;
        sm.c[i] = 0.0f;
    }
    for (int i = tid; i < 4 * 65; i += NTHREADS) {
        const int e = i / 65, k = i - e * 65;
        sm.xw[e * 68 + k] = dWhh[(256 + e) * 65 + k];
    }
    if (tid < 4) {
        sm.xwih[tid]  = dWih[256 + tid];
        sm.xbias[tid] = dbih[256 + tid] + dbhh[256 + tid];
    }
    for (int i = tid; i < 65; i += NTHREADS) sm.linW[i] = linW[i];
    if (tid < bt) sm.xbuf[0][tid] = input[b0 + tid];
    const float lb = linb[0];
    __syncthreads();

    // ---- encoder scan (H=64) ----
    lstm_scan<64, false>(sm, bt, b0, input, eWih, eWhh, ebih, ebhh, nullptr, 0.0f);

    // ---- transition: append Dense(speed) to hidden & cell, zero dec x0 ----
    if (tid < bt) {
        const float sp = denseb[0] + denseW[0] * speed[b0 + tid];
        sm.h[tid * HP + 68] = sp;      // h split layout: col 64 at +68
        sm.c[tid * HP + 64] = sp;      // c linear
        sm.xbuf[0][tid] = 0.0f;
    }
    __syncthreads();

    // ---- decoder scan (H=65) + output projection ----
    lstm_scan<65, true>(sm, bt, b0, target, dWih, dWhh, dbih, dbhh, out, lb);
}

extern "C" void kernel_launch(void* const* d_in, const int* in_sizes, int n_in,
                              void* d_out, int out_size)
{
    const float* input  = (const float*)d_in[0];
    const float* speed  = (const float*)d_in[1];
    const float* target = (const float*)d_in[2];
    const float* eWih   = (const float*)d_in[3];
    const float* eWhh   = (const float*)d_in[4];
    const float* ebih   = (const float*)d_in[5];
    const float* ebhh   = (const float*)d_in[6];
    const float* dWih   = (const float*)d_in[7];
    const float* dWhh   = (const float*)d_in[8];
    const float* dbih   = (const float*)d_in[9];
    const float* dbhh   = (const float*)d_in[10];
    const float* linW   = (const float*)d_in[11];
    const float* linb   = (const float*)d_in[12];
    const float* denseW = (const float*)d_in[13];
    const float* denseb = (const float*)d_in[14];
    float* out = (float*)d_out;

    lstm_seq2seq_kernel<<<NCTA, NTHREADS>>>(
        input, speed, target,
        eWih, eWhh, ebih, ebhh,
        dWih, dWhh, dbih, dbhh,
        linW, linb, denseW, denseb, out);
}